// round 1
// baseline (speedup 1.0000x reference)
#include <cuda_runtime.h>

// BahdanauAttention collapses: softmax over a size-1 axis == 1.0, so
//   context[b, d] = sum_t keys[b, t, d]
// query/Ws/Wh/W are dead. Pure HBM-bound reduction: read 256 MB, write 64 KB.

#define B_SZ 32
#define T_LEN 4096
#define D_DIM 512           // floats
#define D4 (D_DIM / 4)      // 128 float4 per row

// Grid: x = D-chunk (8 chunks of 16 float4 = 64 floats), y = batch (32).
// Block: 256 threads = 16 float4-columns x 16 T-partitions.
// Each thread sums 256 rows of one float4 column; smem tree-reduce partitions.
__global__ __launch_bounds__(256, 8)
void keys_sum_kernel(const float4* __restrict__ keys4, float4* __restrict__ out4) {
    const int tid   = threadIdx.x;
    const int col   = tid & 15;          // 0..15 within chunk
    const int part  = tid >> 4;          // 0..15 T-partition
    const int chunk = blockIdx.x;        // 0..7
    const int b     = blockIdx.y;        // 0..31

    const int col4 = chunk * 16 + col;   // global float4 column 0..127
    // starting element (in float4 units) for this thread's T-slice
    long long idx = ((long long)b * T_LEN + (long long)part * 256) * D4 + col4;

    float4 acc = make_float4(0.f, 0.f, 0.f, 0.f);
    #pragma unroll 8
    for (int i = 0; i < 256; ++i) {
        float4 v = keys4[idx];
        idx += D4;
        acc.x += v.x; acc.y += v.y; acc.z += v.z; acc.w += v.w;
    }

    __shared__ float4 sm[256];
    sm[tid] = acc;
    __syncthreads();

    // reduce across the 16 T-partitions (stride-16 layout keeps per-col sums)
    #pragma unroll
    for (int s = 128; s >= 16; s >>= 1) {
        if (tid < s) {
            float4 o = sm[tid + s];
            float4 m = sm[tid];
            m.x += o.x; m.y += o.y; m.z += o.z; m.w += o.w;
            sm[tid] = m;
        }
        __syncthreads();
    }

    if (tid < 16) {
        out4[(long long)b * D4 + chunk * 16 + tid] = sm[tid];
    }
}

extern "C" void kernel_launch(void* const* d_in, const int* in_sizes, int n_in,
                              void* d_out, int out_size) {
    // metadata order: query[0], keys[1], Ws[2], Wh[3], W[4]; only keys is live.
    const float* keys = (const float*)d_in[1];
    float* out = (float*)d_out;

    dim3 grid(D4 / 16, B_SZ);   // (8, 32) = 256 blocks
    keys_sum_kernel<<<grid, 256>>>((const float4*)keys, (float4*)out);
}

// round 2
// speedup vs baseline: 1.2294x; 1.2294x over previous
#include <cuda_runtime.h>

// BahdanauAttention collapses: softmax over a size-1 axis == 1.0, so
//   context[b, d] = sum_t keys[b, t, d]
// Pure HBM-bound streaming reduction: read 256 MB, write 64 KB.
// R2: raise occupancy 21%->86% (1024 thr/block) to cover DRAM latency.

#define B_SZ 32
#define T_LEN 4096
#define D_DIM 512           // floats
#define D4 (D_DIM / 4)      // 128 float4 per row

// Grid: x = D-chunk (8 chunks of 16 float4 = 64 floats), y = batch (32).
// Block: 1024 threads = 16 float4-columns x 64 T-partitions.
// Each thread streams 64 rows of one float4 column; smem tree-reduce partitions.
__global__ __launch_bounds__(1024, 2)
void keys_sum_kernel(const float4* __restrict__ keys4, float4* __restrict__ out4) {
    const int tid   = threadIdx.x;
    const int col   = tid & 15;          // 0..15 within chunk
    const int part  = tid >> 4;          // 0..63 T-partition
    const int chunk = blockIdx.x;        // 0..7
    const int b     = blockIdx.y;        // 0..31

    const int col4 = chunk * 16 + col;   // global float4 column 0..127
    // starting element (in float4 units) for this thread's T-slice (64 rows)
    long long idx = ((long long)b * T_LEN + (long long)part * 64) * D4 + col4;

    float4 acc = make_float4(0.f, 0.f, 0.f, 0.f);
    #pragma unroll 8
    for (int i = 0; i < 64; ++i) {
        float4 v = __ldcs(&keys4[idx]);   // streaming: no reuse, bypass retention
        idx += D4;
        acc.x += v.x; acc.y += v.y; acc.z += v.z; acc.w += v.w;
    }

    __shared__ float4 sm[1024];
    sm[tid] = acc;
    __syncthreads();

    // reduce across the 64 T-partitions (stride-16 layout keeps per-col sums)
    #pragma unroll
    for (int s = 512; s >= 16; s >>= 1) {
        if (tid < s) {
            float4 o = sm[tid + s];
            float4 m = sm[tid];
            m.x += o.x; m.y += o.y; m.z += o.z; m.w += o.w;
            sm[tid] = m;
        }
        __syncthreads();
    }

    if (tid < 16) {
        out4[(long long)b * D4 + chunk * 16 + tid] = sm[tid];
    }
}

extern "C" void kernel_launch(void* const* d_in, const int* in_sizes, int n_in,
                              void* d_out, int out_size) {
    // metadata order: query[0], keys[1], Ws[2], Wh[3], W[4]; only keys is live.
    const float* keys = (const float*)d_in[1];
    float* out = (float*)d_out;

    dim3 grid(D4 / 16, B_SZ);   // (8, 32) = 256 blocks, one wave
    keys_sum_kernel<<<grid, 1024>>>((const float4*)keys, (float4*)out);
}